// round 17
// baseline (speedup 1.0000x reference)
#include <cuda_runtime.h>
#include <cstdint>

// DynamicLIF persistent kernel for GB300 (sm_103a), round 17.
// Base = R16 (55.8us bench / 49.8us ncu: step-ahead rendezvous via
// S(t) = tau_t*P(t-1) + X(t), TMA tiles, coordinator MLP).
// CHANGE: 5 QUARTER-BUFFERS (8KB each) replace the single 32KB tile.
// Quarter k (= 4t+q) lives in buffer k%5 (parity (k/5)&1) and quarter k+5
// is issued the moment quarter k is FMA-consumed -> TMA runs ~a full step
// ahead; all mbar waits land on already-completed barriers. Step t's
// X-phase waits quarters 4t+4..4t+7 (needed for X(t+1) AND step t+1's
// FMA, which therefore never waits). Static smem ~41KB keeps 4 CTA/SM
// (co-residency 592 >= 544 intact) and stays under the 48KB static limit.
// All tau-feeding arithmetic/order byte-identical to R16 (rel_err 0.0).

#define NB 32          // batch
#define NT 8           // time steps
#define NC 128         // channels
#define HW_ 1024       // H*W
#define CR 32          // C / red
#define THREADS 256
#define RPB 8          // channel rows (slices) per block
#define BPB 16         // streaming blocks per batch
#define NSTREAM (NB * BPB)       // 512
#define NBLOCKS (NSTREAM + NB)   // 544 (32 coordinators)
#define PUBS (BPB * RPB)         // 128 count-releases per round
#define CPAD 64        // 256B stride for g_count (unsigned)
#define SPAD 32        // 256B stride for g_sync (u64)
#define QBYTES 8192    // one quarter: 2 slices = 2048 floats
#define NQBUF 5
#define NQ_TOTAL (NT * 4)        // 32 quarters
#define SM_WARPP 40960
#define SM_WARPX 41216
#define SM_TAU   41472
#define SM_MBARS 41480           // 5 x 8B

__device__ float              g_P[2][NB * NC];   // post-reset sums, round r&1
__device__ float              g_X[2][NB * NC];   // raw x sums, round r&1
__device__ unsigned           g_count[NB * CPAD]; // zero at launch; coord resets at end
__device__ unsigned long long g_sync[NB * SPAD];  // (gen<<32)|tau_bits, monotonic gen

__device__ __forceinline__ unsigned ld_acquire_u32(const unsigned* p) {
    unsigned v;
    asm volatile("ld.acquire.gpu.global.u32 %0, [%1];" : "=r"(v) : "l"(p));
    return v;
}
__device__ __forceinline__ unsigned long long ld_acquire_u64(const unsigned long long* p) {
    unsigned long long v;
    asm volatile("ld.acquire.gpu.global.u64 %0, [%1];" : "=l"(v) : "l"(p));
    return v;
}
__device__ __forceinline__ void st_release_u64(unsigned long long* p, unsigned long long v) {
    asm volatile("st.release.gpu.global.u64 [%0], %1;" :: "l"(p), "l"(v));
}
__device__ __forceinline__ void red_release_add(unsigned* p, unsigned v) {
    asm volatile("red.release.gpu.global.add.u32 [%0], %1;" :: "l"(p), "r"(v));
}
__device__ __forceinline__ unsigned smem_u32(const void* p) {
    return (unsigned)__cvta_generic_to_shared(p);
}
__device__ __forceinline__ void tma_quarter(unsigned dst, const float* src, unsigned mbar) {
    asm volatile("mbarrier.arrive.expect_tx.shared.b64 _, [%0], %1;"
                 :: "r"(mbar), "r"((unsigned)QBYTES) : "memory");
    asm volatile("cp.async.bulk.shared::cta.global.mbarrier::complete_tx::bytes "
                 "[%0], [%1], %2, [%3];"
                 :: "r"(dst), "l"(src), "r"((unsigned)QBYTES), "r"(mbar)
                 : "memory");
}
__device__ __forceinline__ void mbar_wait(unsigned mbar, unsigned parity) {
    unsigned done;
    asm volatile(
        "{\n\t.reg .pred p;\n\t"
        "mbarrier.try_wait.parity.acquire.cta.shared::cta.b64 p, [%1], %2;\n\t"
        "selp.b32 %0, 1, 0, p;\n\t}"
        : "=r"(done) : "r"(mbar), "r"(parity) : "memory");
    if (!done) {
        asm volatile(
            "{\n\t.reg .pred P1;\n\t"
            "LW%=:\n\t"
            "mbarrier.try_wait.parity.acquire.cta.shared::cta.b64 P1, [%0], %1, 0x989680;\n\t"
            "@P1 bra.uni LD%=;\n\t"
            "bra.uni LW%=;\n\t"
            "LD%=:\n\t}"
            :: "r"(mbar), "r"(parity) : "memory");
    }
}

__global__ void __launch_bounds__(THREADS, 4)
lif_kernel(const float* __restrict__ x,
           const float* __restrict__ w1,
           const float* __restrict__ b1,
           const float* __restrict__ w2,
           const float* __restrict__ b2,
           float* __restrict__ out)
{
    __shared__ __align__(128) char s_raw[SM_MBARS + 64];

    const int tid = threadIdx.x;
    const int blk = blockIdx.x;
    const int lane = tid & 31;
    const int warp = tid >> 5;

    // ---------------- coordinator blocks (one per batch) ----------------
    if (blk >= NSTREAM) {
        float* s_w1t  = (float*)s_raw;              // [NC*CR] transposed
        float* s_mean = (float*)(s_raw + 16384);    // [NC]
        float* s_tn   = (float*)(s_raw + 16896);

        const int bb = blk - NSTREAM;
        unsigned*           cnt = &g_count[bb * CPAD];
        unsigned long long* syn = &g_sync[bb * SPAD];

        #pragma unroll
        for (int i = 0; i < (CR * NC) / THREADS; i++) {
            int idx = i * THREADS + tid;
            s_w1t[(idx & 127) * CR + (idx >> 7)] = w1[idx];
        }

        unsigned base_gen = 0;
        if (tid == 0) base_gen = (unsigned)(*(volatile unsigned long long*)syn >> 32);
        __syncthreads();

        float tauk = 0.0f;   // tau_k; unused at k==0
        #pragma unroll 1
        for (int k = 0; k < NT - 1; k++) {
            if (tid == 0) {
                unsigned tgt = (unsigned)PUBS * (unsigned)(k + 1);
                while (ld_acquire_u32(cnt) < tgt) { }
            }
            __syncthreads();   // acquire by t0 + barrier -> round data visible

            const int buf = k & 1;
            if (tid < NC) {
                float Xc = __ldcg(&g_X[buf][bb * NC + tid]);
                float Sc;
                if (k == 0) Sc = Xc;
                else {
                    float Pc = __ldcg(&g_P[buf][bb * NC + tid]);
                    Sc = __fadd_rn(__fmul_rn(tauk, Pc), Xc);
                }
                s_mean[tid] = Sc * (1.0f / 1024.0f);
            }
            __syncthreads();
            if (tid < CR) {
                float acc = b1[tid];
                #pragma unroll
                for (int c = 0; c < NC; c++)
                    acc = fmaf(s_w1t[c * CR + tid], s_mean[c], acc);
                float e = fmaxf(acc, 0.0f);        // relu
                float p = e * w2[tid];
                p += __shfl_xor_sync(0xffffffffu, p, 16);
                p += __shfl_xor_sync(0xffffffffu, p, 8);
                p += __shfl_xor_sync(0xffffffffu, p, 4);
                p += __shfl_xor_sync(0xffffffffu, p, 2);
                p += __shfl_xor_sync(0xffffffffu, p, 1);
                if (tid == 0) {
                    float z = p + b2[0];
                    float tn = 1.0f / (1.0f + expf(-z));   // sigmoid = tau_{k+1}
                    *s_tn = tn;
                    unsigned long long v =
                        ((unsigned long long)(base_gen + (unsigned)(k + 1)) << 32)
                        | (unsigned long long)__float_as_uint(tn);
                    st_release_u64(syn, v);
                }
            }
            __syncthreads();
            tauk = *s_tn;
        }
        if (tid == 0) *(volatile unsigned*)cnt = 0;   // replay-safe reset
        return;
    }

    // ---------------- streaming blocks ----------------
    float (*s_warpP)[RPB] = (float(*)[RPB])(s_raw + SM_WARPP);
    float (*s_warpX)[RPB] = (float(*)[RPB])(s_raw + SM_WARPX);
    float* s_tau = (float*)(s_raw + SM_TAU);
    unsigned long long* s_mbars = (unsigned long long*)(s_raw + SM_MBARS);

    const int b   = blk >> 4;
    const int sub = blk & 15;
    unsigned*           const cnt = &g_count[b * CPAD];
    unsigned long long* const syn = &g_sync[b * SPAD];

    unsigned base_gen = 0;
    if (tid == 0) {
        base_gen = (unsigned)(*(volatile unsigned long long*)syn >> 32);
        #pragma unroll
        for (int j = 0; j < NQBUF; j++)
            asm volatile("mbarrier.init.shared.b64 [%0], 1;"
                         :: "r"(smem_u32(s_mbars + j)) : "memory");
    }
    __syncthreads();

    // Block's contiguous region per step: 8192 floats starting at row_base.
    const size_t row_base = ((size_t)b * NT * NC + (size_t)sub * RPB) * HW_;
    // Source of quarter k: step k/4, quarter (k%4)*2048 floats.
    #define QSRC(k) (x + row_base + (size_t)((k) >> 2) * (NC * HW_) + (size_t)((k) & 3) * 2048)
    #define QDST(k) smem_u32(s_raw + ((k) % NQBUF) * QBYTES)
    #define QMBAR(k) smem_u32(s_mbars + ((k) % NQBUF))
    #define QPAR(k) ((unsigned)((((unsigned)(k)) / NQBUF) & 1u))

    // Prologue: issue quarters 0..4.
    if (tid == 0) {
        #pragma unroll
        for (int k = 0; k < NQBUF; k++)
            tma_quarter(QDST(k), QSRC(k), QMBAR(k));
    }

    // X(0): wait quarters 0..3 and reduce (identical slice order 0..7).
    #pragma unroll
    for (int q = 0; q < 4; q++) {
        mbar_wait(QMBAR(q), QPAR(q));
        const float4* bq = (const float4*)(s_raw + (q % NQBUF) * QBYTES);
        #pragma unroll
        for (int s2 = 0; s2 < 2; s2++) {
            const int i = 2 * q + s2;
            float4 xv = bq[s2 * THREADS + tid];
            float v = (xv.x + xv.y) + (xv.z + xv.w);
            v += __shfl_xor_sync(0xffffffffu, v, 16);
            v += __shfl_xor_sync(0xffffffffu, v, 8);
            v += __shfl_xor_sync(0xffffffffu, v, 4);
            v += __shfl_xor_sync(0xffffffffu, v, 2);
            v += __shfl_xor_sync(0xffffffffu, v, 1);
            if (lane == 0) s_warpX[warp][i] = v;
        }
    }
    __syncthreads();
    if (tid < RPB) {
        float s = 0.f;
        #pragma unroll
        for (int w = 0; w < 8; w++) s += s_warpX[w][tid];
        __stcg(&g_X[0][b * NC + sub * RPB + tid], s);
        red_release_add(cnt, 1u);      // round 0
    }

    float tau = 0.5f;                  // TAU0
    float4 mem[RPB];
    #pragma unroll
    for (int i = 0; i < RPB; i++) mem[i] = make_float4(0.f, 0.f, 0.f, 0.f);

    for (int t = 0; t < NT; t++) {
        float4* op = (float4*)(out + row_base + (size_t)t * NC * HW_);

        // ---- 1) FMA over quarters 4t..4t+3 (waits already done in the
        //         previous step's X-phase / prologue). Issue k+5 after
        //         consuming each pair. Slice order i=0..7 == R16. ----
        #pragma unroll
        for (int g = 0; g < 2; g++) {
            #pragma unroll
            for (int qq = 0; qq < 2; qq++) {
                const int q = 2 * g + qq;
                const int k = 4 * t + q;
                const float4* bq = (const float4*)(s_raw + (k % NQBUF) * QBYTES);
                #pragma unroll
                for (int s2 = 0; s2 < 2; s2++) {
                    const int i = 2 * q + s2;
                    float4 xv = bq[s2 * THREADS + tid];
                    float4 m = mem[i];
                    m.x = __fadd_rn(__fmul_rn(m.x, tau), xv.x);
                    m.y = __fadd_rn(__fmul_rn(m.y, tau), xv.y);
                    m.z = __fadd_rn(__fmul_rn(m.z, tau), xv.z);
                    m.w = __fadd_rn(__fmul_rn(m.w, tau), xv.w);
                    mem[i] = m;
                }
            }
            __syncthreads();   // pair fully consumed -> buffers reusable
            if (tid == 0) {
                const int k1 = 4 * t + 5 + 2 * g;
                const int k2 = k1 + 1;
                if (k1 < NQ_TOTAL) tma_quarter(QDST(k1), QSRC(k1), QMBAR(k1));
                if (k2 < NQ_TOTAL) tma_quarter(QDST(k2), QSRC(k2), QMBAR(k2));
            }
        }

        // ---- 2) spike + output + soft reset; P(t) partials ----
        float part[RPB];
        #pragma unroll
        for (int i = 0; i < RPB; i++) {
            float4 m = mem[i];
            float4 sp;
            sp.x = (m.x > 1.0f) ? 1.0f : 0.0f;
            sp.y = (m.y > 1.0f) ? 1.0f : 0.0f;
            sp.z = (m.z > 1.0f) ? 1.0f : 0.0f;
            sp.w = (m.w > 1.0f) ? 1.0f : 0.0f;
            __stcs(op + i * THREADS + tid, sp);
            m.x = (m.x > 1.0f) ? 0.0f : m.x;
            m.y = (m.y > 1.0f) ? 0.0f : m.y;
            m.z = (m.z > 1.0f) ? 0.0f : m.z;
            m.w = (m.w > 1.0f) ? 0.0f : m.w;
            mem[i] = m;
            part[i] = (m.x + m.y) + (m.z + m.w);
        }

        if (t == NT - 1) break;

        const bool pub = (t <= NT - 3);   // rounds 1..6 at steps 0..5

        if (pub) {
            // P(t) shfl-reduce (identical order).
            #pragma unroll
            for (int i = 0; i < RPB; i++) {
                float v = part[i];
                v += __shfl_xor_sync(0xffffffffu, v, 16);
                v += __shfl_xor_sync(0xffffffffu, v, 8);
                v += __shfl_xor_sync(0xffffffffu, v, 4);
                v += __shfl_xor_sync(0xffffffffu, v, 2);
                v += __shfl_xor_sync(0xffffffffu, v, 1);
                if (lane == 0) s_warpP[warp][i] = v;
            }
        }

        // ---- 3) X-phase: wait quarters 4t+4..4t+7 (pre-wait for step
        //         t+1's FMA too); X(t+1) partials if publishing ----
        #pragma unroll
        for (int q = 0; q < 4; q++) {
            const int k = 4 * t + 4 + q;
            mbar_wait(QMBAR(k), QPAR(k));
            if (pub) {
                const float4* bq = (const float4*)(s_raw + (k % NQBUF) * QBYTES);
                #pragma unroll
                for (int s2 = 0; s2 < 2; s2++) {
                    const int i = 2 * q + s2;
                    float4 xv = bq[s2 * THREADS + tid];
                    float v = (xv.x + xv.y) + (xv.z + xv.w);
                    v += __shfl_xor_sync(0xffffffffu, v, 16);
                    v += __shfl_xor_sync(0xffffffffu, v, 8);
                    v += __shfl_xor_sync(0xffffffffu, v, 4);
                    v += __shfl_xor_sync(0xffffffffu, v, 2);
                    v += __shfl_xor_sync(0xffffffffu, v, 1);
                    if (lane == 0) s_warpX[warp][i] = v;
                }
            }
        }

        if (pub) {
            __syncthreads();   // s_warpP + s_warpX complete
            if (tid < RPB) {
                const int buf = (t + 1) & 1;
                float sp_ = 0.f, sx_ = 0.f;
                #pragma unroll
                for (int w = 0; w < 8; w++) { sp_ += s_warpP[w][tid]; sx_ += s_warpX[w][tid]; }
                __stcg(&g_P[buf][b * NC + sub * RPB + tid], sp_);
                __stcg(&g_X[buf][b * NC + sub * RPB + tid], sx_);
                red_release_add(cnt, 1u);
            }
        }

        // ---- 4) poll tau_{t+1}: released a full step ago in steady state ----
        if (tid == 0) {
            unsigned tgt = base_gen + (unsigned)(t + 1);
            unsigned long long v;
            do {
                v = ld_acquire_u64(syn);
            } while ((int)((unsigned)(v >> 32) - tgt) < 0);
            *s_tau = __uint_as_float((unsigned)v);
        }
        __syncthreads();
        tau = *s_tau;
    }

    // Invalidate mbarriers so the next graph replay re-inits cleanly.
    __syncthreads();
    if (tid == 0) {
        #pragma unroll
        for (int j = 0; j < NQBUF; j++)
            asm volatile("mbarrier.inval.shared.b64 [%0];"
                         :: "r"(smem_u32(s_mbars + j)) : "memory");
    }
}

extern "C" void kernel_launch(void* const* d_in, const int* in_sizes, int n_in,
                              void* d_out, int out_size)
{
    const float* x  = (const float*)d_in[0];
    const float* w1 = (const float*)d_in[1];
    const float* b1 = (const float*)d_in[2];
    const float* w2 = (const float*)d_in[3];
    const float* b2 = (const float*)d_in[4];
    float* out = (float*)d_out;

    lif_kernel<<<NBLOCKS, THREADS>>>(x, w1, b1, w2, b2, out);
}